// round 3
// baseline (speedup 1.0000x reference)
#include <cuda_runtime.h>

typedef unsigned long long u64;
#define DI __device__ __forceinline__

// ---------- packed f32x2 helpers (FFMA2 is PTX-only on sm_103a) ----------
DI u64 pack2(float lo, float hi) {
    u64 r;
    asm("mov.b64 %0, {%1, %2};"
        : "=l"(r) : "r"(__float_as_uint(lo)), "r"(__float_as_uint(hi)));
    return r;
}
DI u64 dup2(float v) {
    u64 r;
    asm("mov.b64 %0, {%1, %1};" : "=l"(r) : "r"(__float_as_uint(v)));
    return r;
}
DI void unpack2(u64 v, unsigned& lo, unsigned& hi) {
    asm("mov.b64 {%0, %1}, %2;" : "=r"(lo), "=r"(hi) : "l"(v));
}
DI u64 fma2(u64 a, u64 b, u64 c) {
    u64 d;
    asm("fma.rn.f32x2 %0, %1, %2, %3;" : "=l"(d) : "l"(a), "l"(b), "l"(c));
    return d;
}

// Neuron-pair packed weights: lane = neuron parity. 28 u64 = 56 regs.
struct Wgt {
    u64 w1x[4], w1y[4], b1[4];   // layer1: (neuron 2k, neuron 2k+1)
    u64 w2[4][4];                // layer2 row j: (W2[j][2k], W2[j][2k+1])
    u64 b2[4];                   // (b2_j, 0)
};

// One 2-D position -> force, via forward signs + 4096-entry table
// (byte-offset index: layer1 neuron i -> bit (8<<i), layer2 j -> (2048<<j)).
DI float2 eval1(float x, float y, const Wgt& W, const char* __restrict__ tab) {
    const u64 X = dup2(x), Y = dup2(y);
    unsigned idx = 0;
    u64 H[4];
#pragma unroll
    for (int k = 0; k < 4; k++) {
        u64 z = fma2(W.w1x[k], X, fma2(W.w1y[k], Y, W.b1[k]));
        unsigned zl, zh;
        unpack2(z, zl, zh);
        idx |= ((unsigned)((int)zl >> 31)) & (8u << (2 * k));
        idx |= ((unsigned)((int)zh >> 31)) & (8u << (2 * k + 1));
        H[k] = pack2(fmaxf(__uint_as_float(zl), 0.f),
                     fmaxf(__uint_as_float(zh), 0.f));
    }
#pragma unroll
    for (int j = 0; j < 4; j++) {
        u64 acc = W.b2[j];
#pragma unroll
        for (int k = 0; k < 4; k++) acc = fma2(W.w2[j][k], H[k], acc);
        unsigned al, ah;
        unpack2(acc, al, ah);
        const float z2 = __uint_as_float(al) + __uint_as_float(ah);
        idx |= ((unsigned)(__float_as_int(z2) >> 31)) & (2048u << j);
    }
    return *(const float2*)(tab + idx);
}

__global__ void __launch_bounds__(128, 5) toy_force_kernel(
    const float4* __restrict__ pos,
    const float*  __restrict__ W1,   // [8,2]
    const float*  __restrict__ b1,   // [8]
    const float*  __restrict__ W2,   // [4,8]
    const float*  __restrict__ b2,   // [4]
    const float*  __restrict__ W3,   // [2,4]
    float4*       __restrict__ out,
    int npairs)
{
    __shared__ float  u_s[16][8];    // u(m2)_i = sum_{j active} (-v3_j) * W2[j][i]
    __shared__ float2 ftab[4096];    // force per 12-bit (m1,m2) sign pattern

    const int tid = threadIdx.x;

    // ---- u table: one (m2, i) per thread ----
    {
        const int i = tid & 7, m = tid >> 3;   // m in [0,16)
        float s = 0.f;
#pragma unroll
        for (int j = 0; j < 4; j++) {
            const float v3n = -(__ldg(&W3[j]) + __ldg(&W3[4 + j]));  // fold -grad
            if (!((m >> j) & 1)) s += v3n * __ldg(&W2[8 * j + i]);
        }
        u_s[m][i] = s;
    }
    __syncthreads();

    // ---- 4096-entry force table: f = sum_{i: bit clear} u_i * W1[i,:] ----
    {
        float w1c[16];
#pragma unroll
        for (int t = 0; t < 16; t++) w1c[t] = __ldg(&W1[t]);
        for (int e = tid; e < 4096; e += blockDim.x) {
            const int m2 = e >> 8;
            float fx = 0.f, fy = 0.f;
#pragma unroll
            for (int i = 0; i < 8; i++) {
                const float msk = ((e >> i) & 1) ? 0.f : 1.f;
                const float ui = msk * u_s[m2][i];
                fx = fmaf(ui, w1c[2 * i], fx);
                fy = fmaf(ui, w1c[2 * i + 1], fy);
            }
            ftab[e] = make_float2(fx, fy);
        }
    }

    // ---- weights, neuron-pair packed (56 regs) ----
    Wgt W;
#pragma unroll
    for (int k = 0; k < 4; k++) {
        W.w1x[k] = pack2(__ldg(&W1[4 * k]),     __ldg(&W1[4 * k + 2]));
        W.w1y[k] = pack2(__ldg(&W1[4 * k + 1]), __ldg(&W1[4 * k + 3]));
        W.b1[k]  = pack2(__ldg(&b1[2 * k]),     __ldg(&b1[2 * k + 1]));
    }
#pragma unroll
    for (int j = 0; j < 4; j++) {
#pragma unroll
        for (int k = 0; k < 4; k++)
            W.w2[j][k] = pack2(__ldg(&W2[8 * j + 2 * k]),
                               __ldg(&W2[8 * j + 2 * k + 1]));
        W.b2[j] = pack2(__ldg(&b2[j]), 0.f);
    }
    __syncthreads();

    const char* tab = (const char*)ftab;
    const int stride = gridDim.x * blockDim.x;

    int k = blockIdx.x * blockDim.x + tid;
    if (k >= npairs) return;

    float4 p = pos[k];
    for (;;) {
        const int kn = k + stride;
        const bool more = kn < npairs;
        float4 pn;
        if (more) pn = pos[kn];          // prefetch next tile

        const float2 f0 = eval1(p.x, p.y, W, tab);   // two independent evals
        const float2 f1 = eval1(p.z, p.w, W, tab);   // -> ILP 2
        out[k] = make_float4(f0.x, f0.y, f1.x, f1.y);

        if (!more) break;
        k = kn;
        p = pn;
    }
}

extern "C" void kernel_launch(void* const* d_in, const int* in_sizes, int n_in,
                              void* d_out, int out_size) {
    const float* pos = (const float*)d_in[0];
    const float* W1  = (const float*)d_in[1];
    const float* b1  = (const float*)d_in[2];
    const float* W2  = (const float*)d_in[3];
    const float* b2  = (const float*)d_in[4];
    const float* W3  = (const float*)d_in[5];
    float* out = (float*)d_out;

    const int npairs = in_sizes[0] / 4;   // one float4 = 2 positions

    const int threads = 128;
    const int blocks  = 740;              // 148 SMs x 5 CTAs
    toy_force_kernel<<<blocks, threads>>>(
        (const float4*)pos, W1, b1, W2, b2, W3, (float4*)out, npairs);
}